// round 17
// baseline (speedup 1.0000x reference)
#include <cuda_runtime.h>
#include <cuda.h>
#if defined(__has_include)
#if __has_include(<cudaTypedefs.h>)
#include <cudaTypedefs.h>
#endif
#endif
#include <cuda_bf16.h>
#include <cuda_fp16.h>
#include <cstddef>
#include <cstdint>
#include <math.h>

// ---------------------------------------------------------------------------
// Problem constants
// ---------------------------------------------------------------------------
#define NS 10000
#define NW 30000
#define ND 200
#define DIN 768
#define HC1 256
#define H1  4
#define C1  64
#define OUT2 256
#define PROJ1 128
#define PROJ2 128

typedef CUresult (CUDAAPI *tmEncode_t)(
    CUtensorMap*, CUtensorMapDataType, cuuint32_t, void*,
    const cuuint64_t*, const cuuint64_t*, const cuuint32_t*, const cuuint32_t*,
    CUtensorMapInterleave, CUtensorMapSwizzle, CUtensorMapL2promotion,
    CUtensorMapFloatOOBfill);

// ---------------------------------------------------------------------------
// Static device scratch
// ---------------------------------------------------------------------------
__device__ __half g_M [(size_t)NS * 1152];       // s msgs + fused s-logits (fp16)
__device__ __half g_Mw[(size_t)NW * HC1];
__device__ __half g_Md[(size_t)ND * HC1];
__device__ float g_acc4 [(size_t)4 * NS * HC1];  // conv1 dst-S accumulators
__device__ float g_acc4b[(size_t)4 * NS * HC1];  // conv2 dst-S accumulators
__device__ float g_accw[(size_t)NW * HC1];
__device__ float g_accd[(size_t)ND * HC1];
__device__ float g_den [(size_t)6 * NW * H1];    // conv1 denominators
__device__ float g_den2[(size_t)4 * NS];         // conv2 denominators (H=1)
__device__ float g_Vs [DIN * 32];
__device__ float g_Vw [DIN * 8];
__device__ float g_Vd [DIN * 8];
__device__ float g_V2s[HC1 * 8];
__device__ float g_V2w[HC1 * 8];
__device__ float g_V2d[HC1 * 8];
__device__ __half g_Lw [(size_t)NW * 8];
__device__ __half g_Ld [(size_t)ND * 8];
__device__ __half g_L2w[(size_t)NW * 8];
__device__ __half g_L2d[(size_t)ND * 8];

// fp16 A planes (hi first, lo at +planeElems)
__device__ __half g_xsp[2 * (size_t)NS * DIN];
__device__ __half g_xwp[2 * (size_t)NW * DIN];
__device__ __half g_xdp[2 * (size_t)ND * DIN];
__device__ __half g_hsp[2 * (size_t)NS * DIN];
__device__ __half g_hwp[2 * (size_t)NW * DIN];
__device__ __half g_hdp[2 * (size_t)ND * DIN];
__device__ __half g_s1p[2 * (size_t)NS * HC1];
__device__ __half g_w1p[2 * (size_t)NW * HC1];
__device__ __half g_d1p[2 * (size_t)ND * HC1];
__device__ __half g_sop[2 * (size_t)NS * OUT2];
__device__ __half g_p1p[2 * (size_t)NS * PROJ1];
// fp16 B planes (single plane): B1 = [7][256][768] (0-5 weights, 6 s-logit V)
#define PLANE1 ((size_t)7 * 256 * 768)
#define PLANE2 ((size_t)7 * 256 * 256)
__device__ __half g_B1p[PLANE1];
__device__ __half g_B2p[PLANE2];
__device__ __half g_Wlp [(size_t)3 * DIN * DIN];
__device__ __half g_Wp1p[(size_t)PROJ1 * OUT2];
__device__ __half g_Wp2p[(size_t)PROJ2 * PROJ1];

// ---------------------------------------------------------------------------
// Helpers
// ---------------------------------------------------------------------------
__device__ __forceinline__ void split2h(float v0, float v1, unsigned& hi, unsigned& lo) {
    __half2 h2 = __floats2half2_rn(v0, v1);
    float h0 = __low2float(h2), h1 = __high2float(h2);
    __half2 l2 = __floats2half2_rn(v0 - h0, v1 - h1);
    hi = *reinterpret_cast<unsigned*>(&h2);
    lo = *reinterpret_cast<unsigned*>(&l2);
}
__device__ __forceinline__ void mma16816h(float* c, const unsigned* a, const unsigned* b) {
    asm volatile(
        "mma.sync.aligned.m16n8k16.row.col.f32.f16.f16.f32 "
        "{%0,%1,%2,%3}, {%4,%5,%6,%7}, {%8,%9}, {%0,%1,%2,%3};"
        : "+f"(c[0]), "+f"(c[1]), "+f"(c[2]), "+f"(c[3])
        : "r"(a[0]), "r"(a[1]), "r"(a[2]), "r"(a[3]), "r"(b[0]), "r"(b[1]));
}
__device__ __forceinline__ void mbar_wait(unsigned mbar, unsigned ph) {
    asm volatile(
        "{\n\t.reg .pred P1;\n\t"
        "WAIT_LOOP_%=:\n\t"
        "mbarrier.try_wait.parity.acquire.cta.shared::cta.b64 P1, [%0], %1, 0x989680;\n\t"
        "@P1 bra.uni WAIT_DONE_%=;\n\t"
        "bra.uni WAIT_LOOP_%=;\n\t"
        "WAIT_DONE_%=:\n\t}"
        :: "r"(mbar), "r"(ph) : "memory");
}
__device__ __forceinline__ unsigned lds_u32(unsigned a) {
    unsigned v; asm volatile("ld.shared.u32 %0, [%1];" : "=r"(v) : "r"(a)); return v;
}
__device__ __forceinline__ unsigned swz64(unsigned x) {
    return x ^ ((x >> 3) & 0x30u);
}

// ---------------------------------------------------------------------------
// Conversion kernels
// ---------------------------------------------------------------------------
__global__ void convert_a_kernel(const float* __restrict__ X,
                                 __half* __restrict__ hi,
                                 __half* __restrict__ lo, size_t n2)
{
    size_t i = (size_t)blockIdx.x * blockDim.x + threadIdx.x;
    if (i >= n2) return;
    float2 v = *reinterpret_cast<const float2*>(X + i * 2);
    unsigned h, l;
    split2h(v.x, v.y, h, l);
    *reinterpret_cast<unsigned*>(hi + i * 2) = h;
    *reinterpret_cast<unsigned*>(lo + i * 2) = l;
}

// W fp32 [T][K][N] -> fp16 plane [T][N][K]
__global__ void convert_w_kernel(const float* __restrict__ W,
                                 __half* __restrict__ out, int K, int N)
{
    __shared__ float tile[32][33];
    int t = blockIdx.z;
    const float* Wt = W + (size_t)t * K * N;
    __half* ot = out + (size_t)t * N * K;
    int k0 = blockIdx.y * 32, n0 = blockIdx.x * 32;
    for (int dy = threadIdx.y; dy < 32; dy += 8)
        tile[dy][threadIdx.x] = Wt[(size_t)(k0 + dy) * N + n0 + threadIdx.x];
    __syncthreads();
    for (int dy = threadIdx.y; dy < 32; dy += 8) {
        int n = n0 + dy, k = k0 + threadIdx.x;
        ot[(size_t)n * K + k] = __float2half_rn(tile[threadIdx.x][dy]);
    }
}

// packed V fp32 [K][ldv] -> B-plane rows: out[r*K + d] from V[d*ldv + r]
__global__ void v2b_kernel(const float* __restrict__ V, int ldv, int rows,
                           __half* __restrict__ out, int K)
{
    int i = blockIdx.x * blockDim.x + threadIdx.x;
    if (i >= rows * K) return;
    int r = i / K, d = i % K;
    out[(size_t)r * K + d] = __float2half_rn(V[(size_t)d * ldv + r]);
}

// ---------------------------------------------------------------------------
// FP16x2 GEMM, TMA-fed: D = (Ah+Al) @ Bh. Per-group (type,rowOff) columns.
// Stage: Ah 8K | Al 8K | Bh 8K = 24KB (SW64, 64B rows). 128x128x32 tile.
// Outputs: fp32 C, fp16 C16, or fp16 hi/lo planes (whichever non-null).
// ---------------------------------------------------------------------------
#define GSTAGES 4
#define GSTAGE_BYTES 24576
#define GSMEM_TOTAL (GSTAGES * GSTAGE_BYTES + 64)

struct GMap { int t[10]; int off[10]; };

__global__ void __launch_bounds__(256, 2)
gemm_fp16_tma_kernel(const __grid_constant__ CUtensorMap tAh,
                     const __grid_constant__ CUtensorMap tAl,
                     const __grid_constant__ CUtensorMap tBh,
                     const float* __restrict__ bias, float* __restrict__ C,
                     __half* __restrict__ C16,
                     __half* __restrict__ outHi, __half* __restrict__ outLo,
                     int M, int N, int K, int relu, GMap gm)
{
    extern __shared__ __align__(1024) unsigned char smraw[];
    const int tid = threadIdx.x;
    const int wid = tid >> 5;
    const int lane = tid & 31;
    const int wm = (wid & 1) * 64;
    const int wn = (wid >> 1) * 32;
    const int rowBase = blockIdx.y * 128;
    const int colBase = blockIdx.x * 128;
    const int tcoord = gm.t[blockIdx.x];
    const int nOff = gm.off[blockIdx.x];

    const unsigned sbase = (unsigned)__cvta_generic_to_shared(smraw);
    const unsigned mb = sbase + GSTAGES * GSTAGE_BYTES;

    if (tid == 0) {
#pragma unroll
        for (int s = 0; s < GSTAGES; ++s)
            asm volatile("mbarrier.init.shared.b64 [%0], 1;" :: "r"(mb + s * 8) : "memory");
    }
    __syncthreads();

    const int ntiles = K / 32;

    auto issue = [&](int kt, int s) {
        unsigned stage = sbase + s * GSTAGE_BYTES;
        asm volatile("mbarrier.arrive.expect_tx.shared.b64 _, [%0], %1;"
                     :: "r"(mb + s * 8), "r"(24576u) : "memory");
        asm volatile(
            "cp.async.bulk.tensor.3d.shared::cta.global.tile.mbarrier::complete_tx::bytes "
            "[%0], [%1, {%2, %3, %4}], [%5];"
            :: "r"(stage), "l"(&tAh), "r"(kt * 32), "r"(rowBase), "r"(0),
               "r"(mb + s * 8) : "memory");
        asm volatile(
            "cp.async.bulk.tensor.3d.shared::cta.global.tile.mbarrier::complete_tx::bytes "
            "[%0], [%1, {%2, %3, %4}], [%5];"
            :: "r"(stage + 8192), "l"(&tAl), "r"(kt * 32), "r"(rowBase), "r"(0),
               "r"(mb + s * 8) : "memory");
        asm volatile(
            "cp.async.bulk.tensor.3d.shared::cta.global.tile.mbarrier::complete_tx::bytes "
            "[%0], [%1, {%2, %3, %4}], [%5];"
            :: "r"(stage + 16384), "l"(&tBh), "r"(kt * 32), "r"(nOff), "r"(tcoord),
               "r"(mb + s * 8) : "memory");
    };

    if (tid == 0) {
        int np = ntiles < GSTAGES ? ntiles : GSTAGES;
        for (int s = 0; s < np; ++s) issue(s, s);
    }

    float acc[4][4][4];
#pragma unroll
    for (int i = 0; i < 4; i++)
#pragma unroll
        for (int j = 0; j < 4; j++)
#pragma unroll
            for (int l = 0; l < 4; l++) acc[i][j][l] = 0.f;

    const int kq = (lane & 3) * 2;
    const int gq = lane >> 2;

    for (int t = 0; t < ntiles; ++t) {
        const int s = t % GSTAGES;
        mbar_wait(mb + s * 8, (unsigned)((t / GSTAGES) & 1));

        const unsigned Ahi = sbase + s * GSTAGE_BYTES;
        const unsigned Alo = Ahi + 8192;
        const unsigned Bhi = Ahi + 16384;
#pragma unroll
        for (int half = 0; half < 2; ++half) {
            const int b0 = (half * 16 + kq) * 2;
            const int b8 = b0 + 16;
            unsigned bh[4][2];
#pragma unroll
            for (int nt = 0; nt < 4; ++nt) {
                unsigned r = (unsigned)(wn + nt * 8 + gq) * 64u;
                bh[nt][0] = lds_u32(Bhi + swz64(r + b0));
                bh[nt][1] = lds_u32(Bhi + swz64(r + b8));
            }
#pragma unroll
            for (int mt = 0; mt < 4; ++mt) {
                unsigned r0 = (unsigned)(wm + mt * 16 + gq) * 64u;
                unsigned r8 = r0 + 8 * 64u;
                unsigned ah[4], al[4];
                ah[0] = lds_u32(Ahi + swz64(r0 + b0));
                ah[1] = lds_u32(Ahi + swz64(r8 + b0));
                ah[2] = lds_u32(Ahi + swz64(r0 + b8));
                ah[3] = lds_u32(Ahi + swz64(r8 + b8));
                al[0] = lds_u32(Alo + swz64(r0 + b0));
                al[1] = lds_u32(Alo + swz64(r8 + b0));
                al[2] = lds_u32(Alo + swz64(r0 + b8));
                al[3] = lds_u32(Alo + swz64(r8 + b8));
#pragma unroll
                for (int nt = 0; nt < 4; ++nt) {
                    mma16816h(acc[mt][nt], ah, bh[nt]);
                    mma16816h(acc[mt][nt], al, bh[nt]);
                }
            }
        }
        __syncthreads();
        if (tid == 0 && t + GSTAGES < ntiles) issue(t + GSTAGES, s);
    }

    // epilogue
#pragma unroll
    for (int mt = 0; mt < 4; ++mt) {
        int r0 = rowBase + wm + mt * 16 + gq;
#pragma unroll
        for (int nt = 0; nt < 4; ++nt) {
            int c0 = colBase + wn + nt * 8 + 2 * (lane & 3);
            float b0 = bias ? bias[c0] : 0.f;
            float b1v = bias ? bias[c0 + 1] : 0.f;
#pragma unroll
            for (int half = 0; half < 2; ++half) {
                int r = r0 + half * 8;
                if (r >= M) continue;
                float v0 = acc[mt][nt][half * 2 + 0] + b0;
                float v1 = acc[mt][nt][half * 2 + 1] + b1v;
                if (relu) { v0 = fmaxf(v0, 0.f); v1 = fmaxf(v1, 0.f); }
                if (C) *reinterpret_cast<float2*>(&C[(size_t)r * N + c0]) = make_float2(v0, v1);
                if (C16) {
                    __half2 hv = __floats2half2_rn(v0, v1);
                    *reinterpret_cast<unsigned*>(&C16[(size_t)r * N + c0]) =
                        *reinterpret_cast<unsigned*>(&hv);
                }
                if (outHi) {
                    unsigned h, l;
                    split2h(v0, v1, h, l);
                    *reinterpret_cast<unsigned*>(&outHi[(size_t)r * N + c0]) = h;
                    *reinterpret_cast<unsigned*>(&outLo[(size_t)r * N + c0]) = l;
                }
            }
        }
    }
}

// ---------------------------------------------------------------------------
// Fold (warp-per-output) into packed V matrices
// ---------------------------------------------------------------------------
struct FMap { float* base[6]; int coff[6]; int ld[6]; };

__global__ void fold_kernel(const float* __restrict__ W, const float* __restrict__ a,
                            FMap map, int Din, int H, int C, int total)
{
    int gw = (blockIdx.x * blockDim.x + threadIdx.x) >> 5;
    int lane = threadIdx.x & 31;
    if (gw >= total) return;
    int h = gw % H;
    int d = (gw / H) % Din;
    int t = gw / (H * Din);
    const float* Wt = W + (size_t)t * Din * H * C + (size_t)d * H * C + (size_t)h * C;
    const float* at = a + (size_t)t * H * C + (size_t)h * C;
    float s = 0.f;
    for (int c = lane; c < C; c += 32) s = fmaf(Wt[c], at[c], s);
#pragma unroll
    for (int o = 16; o > 0; o >>= 1) s += __shfl_xor_sync(0xffffffffu, s, o);
    if (lane == 0)
        map.base[t][(size_t)d * map.ld[t] + map.coff[t] + h] = s;
}

// ---------------------------------------------------------------------------
// Plane-input batched logit (NC=8): Y[n,0:8] = (Xhi+Xlo)[n,:] @ V  (fp16 out)
// ---------------------------------------------------------------------------
__global__ void logit8p_kernel(const __half* __restrict__ Xhi,
                               const __half* __restrict__ Xlo,
                               const float* __restrict__ V,
                               __half* __restrict__ Y, int Nrows, int Din)
{
    extern __shared__ float vsh[];
    for (int i = threadIdx.x; i < Din * 8; i += blockDim.x) {
        int d = i / 8, c = i % 8;
        vsh[d * 9 + c] = V[i];
    }
    __syncthreads();
    int warp = (blockIdx.x * blockDim.x + threadIdx.x) >> 5;
    int lane = threadIdx.x & 31;
    if (warp >= Nrows) return;
    float acc[8];
#pragma unroll
    for (int c = 0; c < 8; ++c) acc[c] = 0.f;
    const __half2* hr = reinterpret_cast<const __half2*>(Xhi + (size_t)warp * Din);
    const __half2* lr = reinterpret_cast<const __half2*>(Xlo + (size_t)warp * Din);
    const int Dh = Din >> 1;
    for (int dp = lane; dp < Dh; dp += 32) {
        __half2 h = hr[dp], l = lr[dp];
        float x0 = __low2float(h) + __low2float(l);
        float x1 = __high2float(h) + __high2float(l);
        const float* v0 = &vsh[(dp * 2) * 9];
        const float* v1 = &vsh[(dp * 2 + 1) * 9];
#pragma unroll
        for (int c = 0; c < 8; ++c) acc[c] = fmaf(x1, v1[c], fmaf(x0, v0[c], acc[c]));
    }
#pragma unroll
    for (int c = 0; c < 8; ++c) {
#pragma unroll
        for (int o = 16; o > 0; o >>= 1) acc[c] += __shfl_xor_sync(0xffffffffu, acc[c], o);
    }
    if (lane < 8) Y[(size_t)warp * 8 + lane] = __float2half_rn(acc[lane]);
}

// ---------------------------------------------------------------------------
// Fused single-pass edge kernel (fp16 msgs + logits, fp32 accumulation)
// ---------------------------------------------------------------------------
__device__ __forceinline__ void red_add_v4(float* p, float x, float y, float z, float w) {
    asm volatile("red.global.add.v4.f32 [%0], {%1,%2,%3,%4};"
                 :: "l"(__cvta_generic_to_global(p)),
                    "f"(x), "f"(y), "f"(z), "f"(w) : "memory");
}

struct EType {
    const int* ei; int E;
    const __half* Ys; const __half* Yd;
    float* den; const __half* msg; float* acc;
    int lds, offS, ldd, offD, ldm, moff;
};
struct EParams {
    EType t[6];
    int start[7];
    int nT, H, HC, cshift;
};

__global__ void edge_fused_kernel(EParams P)
{
    int gw = (blockIdx.x * blockDim.x + threadIdx.x) >> 5;
    int lane = threadIdx.x & 31;
    if (gw >= P.start[P.nT]) return;
    int t = 0;
    while (gw >= P.start[t + 1]) ++t;
    const EType& e = P.t[t];
    int le = gw - P.start[t];
    int s = e.ei[le], d = e.ei[e.E + le];
    float w = 0.f;
    if (lane < P.H) {
        float v = __half2float(e.Ys[(size_t)s * e.lds + e.offS + lane])
                + __half2float(e.Yd[(size_t)d * e.ldd + e.offD + lane]);
        v = v > 0.f ? v : 0.2f * v;
        w = expf(v);
        atomicAdd(&e.den[(size_t)d * P.H + lane], w);
    }
    const __half* m = e.msg + (size_t)s * e.ldm + e.moff;
    float* a = e.acc + (size_t)d * P.HC;
#pragma unroll
    for (int base = 0; base < 256; base += 128) {
        int col = base + lane * 4;
        int h = col >> P.cshift;
        float al = __shfl_sync(0xffffffffu, w, h);
        __half2 m0 = *reinterpret_cast<const __half2*>(m + col);
        __half2 m1 = *reinterpret_cast<const __half2*>(m + col + 2);
        float2 f0 = __half22float2(m0);
        float2 f1 = __half22float2(m1);
        red_add_v4(a + col, al * f0.x, al * f0.y, al * f1.x, al * f1.y);
    }
}

// ---------------------------------------------------------------------------
// Combine + (relu) + LayerNorm; optional fp32 / plane outputs
// ---------------------------------------------------------------------------
__global__ void combine_ln_kernel(float* __restrict__ out,
    __half* __restrict__ outHi, __half* __restrict__ outLo,
    const float* a0, const float* a1, const float* a2, const float* a3,
    const float* d0, const float* d1, const float* d2, const float* d3,
    int nT, const float* __restrict__ bias, int bt0, int bt1, int bt2, int bt3,
    int H, int relu)
{
    int row = blockIdx.x;
    int tid = threadIdx.x;
    int h = (H == 4) ? (tid >> 6) : 0;
    size_t ro = (size_t)row * 256 + tid;
    size_t dn = (size_t)row * H + h;
    float v = a0[ro] / (d0[dn] + 1e-16f) + bias[(size_t)bt0 * 256 + tid];
    if (nT > 1) v += a1[ro] / (d1[dn] + 1e-16f) + bias[(size_t)bt1 * 256 + tid];
    if (nT > 2) v += a2[ro] / (d2[dn] + 1e-16f) + bias[(size_t)bt2 * 256 + tid];
    if (nT > 3) v += a3[ro] / (d3[dn] + 1e-16f) + bias[(size_t)bt3 * 256 + tid];
    if (relu) v = fmaxf(v, 0.f);

    __shared__ float red[8];
    float s = v;
#pragma unroll
    for (int o = 16; o > 0; o >>= 1) s += __shfl_xor_sync(0xffffffffu, s, o);
    if ((tid & 31) == 0) red[tid >> 5] = s;
    __syncthreads();
    float tot = 0.f;
#pragma unroll
    for (int i = 0; i < 8; i++) tot += red[i];
    float mu = tot * (1.f / 256.f);
    float dv = v - mu;
    __syncthreads();
    s = dv * dv;
#pragma unroll
    for (int o = 16; o > 0; o >>= 1) s += __shfl_xor_sync(0xffffffffu, s, o);
    if ((tid & 31) == 0) red[tid >> 5] = s;
    __syncthreads();
    tot = 0.f;
#pragma unroll
    for (int i = 0; i < 8; i++) tot += red[i];
    float var = tot * (1.f / 256.f);
    float o_ = dv * rsqrtf(var + 1e-5f);
    if (out) out[(size_t)row * 256 + tid] = o_;
    if (outHi) {
        float on = __shfl_xor_sync(0xffffffffu, o_, 1);
        if ((tid & 1) == 0) {
            unsigned hh, ll;
            split2h(o_, on, hh, ll);
            *reinterpret_cast<unsigned*>(&outHi[(size_t)row * 256 + tid]) = hh;
            *reinterpret_cast<unsigned*>(&outLo[(size_t)row * 256 + tid]) = ll;
        }
    }
}

// ---------------------------------------------------------------------------
// Host orchestration
// ---------------------------------------------------------------------------
static tmEncode_t get_encoder()
{
    static tmEncode_t fn = nullptr;
    if (!fn) {
        cudaDriverEntryPointQueryResult qr;
        cudaGetDriverEntryPoint("cuTensorMapEncodeTiled", (void**)&fn,
                                cudaEnableDefault, &qr);
    }
    return fn;
}

// Streams/events created at static-init time.
struct StreamPack {
    cudaStream_t s1 = nullptr;
    cudaEvent_t evF = nullptr, evA = nullptr, evB1 = nullptr, evB = nullptr,
                evE1 = nullptr, evC = nullptr;
    StreamPack() {
        if (cudaStreamCreateWithFlags(&s1, cudaStreamNonBlocking) != cudaSuccess) { s1 = nullptr; return; }
        if (cudaEventCreateWithFlags(&evF, cudaEventDisableTiming) != cudaSuccess ||
            cudaEventCreateWithFlags(&evA, cudaEventDisableTiming) != cudaSuccess ||
            cudaEventCreateWithFlags(&evB1, cudaEventDisableTiming) != cudaSuccess ||
            cudaEventCreateWithFlags(&evB, cudaEventDisableTiming) != cudaSuccess ||
            cudaEventCreateWithFlags(&evE1, cudaEventDisableTiming) != cudaSuccess ||
            cudaEventCreateWithFlags(&evC, cudaEventDisableTiming) != cudaSuccess) {
            s1 = nullptr;
        }
    }
};
static StreamPack g_sp;

static void make_tm_h(CUtensorMap* tm, const void* base,
                      uint64_t K, uint64_t rows, uint64_t T)
{
    cuuint64_t dims[3] = {K, rows, T};
    cuuint64_t strides[2] = {K * 2, rows * K * 2};
    cuuint32_t box[3] = {32, 128, 1};
    cuuint32_t es[3] = {1, 1, 1};
    get_encoder()(tm, CU_TENSOR_MAP_DATA_TYPE_FLOAT16, 3, (void*)base,
                  dims, strides, box, es,
                  CU_TENSOR_MAP_INTERLEAVE_NONE, CU_TENSOR_MAP_SWIZZLE_64B,
                  CU_TENSOR_MAP_L2_PROMOTION_L2_128B,
                  CU_TENSOR_MAP_FLOAT_OOB_FILL_NONE);
}

static void gemm_h(cudaStream_t st,
                   const __half* Ap, size_t aPlane,
                   const __half* Bp, uint64_t bRows, uint64_t bT,
                   const float* bias, float* C, __half* C16,
                   __half* outHi, __half* outLo,
                   int M, int N, int K, int relu, const GMap& gm)
{
    static bool attr_done = false;
    if (!attr_done) {
        cudaFuncSetAttribute(gemm_fp16_tma_kernel,
                             cudaFuncAttributeMaxDynamicSharedMemorySize, GSMEM_TOTAL);
        attr_done = true;
    }
    CUtensorMap tAh, tAl, tBh;
    make_tm_h(&tAh, Ap, (uint64_t)K, (uint64_t)M, 1);
    make_tm_h(&tAl, Ap + aPlane, (uint64_t)K, (uint64_t)M, 1);
    make_tm_h(&tBh, Bp, (uint64_t)K, bRows, bT);
    dim3 grid(N / 128, (M + 127) / 128);
    gemm_fp16_tma_kernel<<<grid, 256, GSMEM_TOTAL, st>>>(tAh, tAl, tBh, bias, C, C16,
                                                         outHi, outLo, M, N, K, relu, gm);
}

static GMap gm_uniform(int type, int ngroups)
{
    GMap m{};
    for (int i = 0; i < ngroups; i++) { m.t[i] = type; m.off[i] = i * 128; }
    return m;
}

static inline void conv_a(cudaStream_t st, const float* X, __half* p, size_t n)
{
    size_t n2 = n / 2;
    convert_a_kernel<<<(unsigned)((n2 + 255) / 256), 256, 0, st>>>(X, p, p + n, n2);
}

extern "C" void kernel_launch(void* const* d_in, const int* in_sizes, int n_in,
                              void* d_out, int out_size)
{
    const float* x_sent = (const float*)d_in[0];
    const float* x_word = (const float*)d_in[1];
    const float* x_doc  = (const float*)d_in[2];
    const int* ei_ss = (const int*)d_in[3];
    const int* ei_sa = (const int*)d_in[4];
    const int* ei_ws = (const int*)d_in[5];
    const int* ei_sw = (const int*)d_in[6];
    const int* ei_ds = (const int*)d_in[7];
    const int* ei_sd = (const int*)d_in[8];
    const float* Wls = (const float*)d_in[9];   const float* bls = (const float*)d_in[10];
    const float* Wlw = (const float*)d_in[11];  const float* blw = (const float*)d_in[12];
    const float* Wld = (const float*)d_in[13];  const float* bld = (const float*)d_in[14];
    const float* W1s = (const float*)d_in[15];
    const float* W1d_ = (const float*)d_in[16];
    const float* a1s = (const float*)d_in[17];
    const float* a1d = (const float*)d_in[18];
    const float* b1  = (const float*)d_in[19];
    const float* W2s = (const float*)d_in[20];
    const float* W2d_ = (const float*)d_in[21];
    const float* a2s = (const float*)d_in[22];
    const float* a2d = (const float*)d_in[23];
    const float* b2  = (const float*)d_in[24];
    const float* Wp1 = (const float*)d_in[25];  const float* bp1 = (const float*)d_in[26];
    const float* Wp2 = (const float*)d_in[27];  const float* bp2 = (const float*)d_in[28];

    const int E_ss = in_sizes[3] / 2, E_sa = in_sizes[4] / 2, E_ws = in_sizes[5] / 2;
    const int E_sw = in_sizes[6] / 2, E_ds = in_sizes[7] / 2, E_sd = in_sizes[8] / 2;

    float* out_f = (float*)d_out;

    __half *p_M, *p_Mw, *p_Md;
    float *p_acc4, *p_acc4b, *p_accw, *p_accd, *p_den, *p_den2;
    float *p_Vs, *p_Vw, *p_Vd, *p_V2s, *p_V2w, *p_V2d;
    __half *p_Lw, *p_Ld, *p_L2w, *p_L2d;
    __half *p_xsp, *p_xwp, *p_xdp, *p_hsp, *p_hwp, *p_hdp;
    __half *p_s1p, *p_w1p, *p_d1p, *p_sop, *p_p1p;
    __half *p_Wlp, *p_B1p, *p_B2p, *p_Wp1p, *p_Wp2p;
    cudaGetSymbolAddress((void**)&p_M,    g_M);
    cudaGetSymbolAddress((void**)&p_Mw,   g_Mw);
    cudaGetSymbolAddress((void**)&p_Md,   g_Md);
    cudaGetSymbolAddress((void**)&p_acc4, g_acc4);
    cudaGetSymbolAddress((void**)&p_acc4b, g_acc4b);
    cudaGetSymbolAddress((void**)&p_accw, g_accw);
    cudaGetSymbolAddress((void**)&p_accd, g_accd);
    cudaGetSymbolAddress((void**)&p_den,  g_den);
    cudaGetSymbolAddress((void**)&p_den2, g_den2);
    cudaGetSymbolAddress((void**)&p_Vs,  g_Vs);
    cudaGetSymbolAddress((void**)&p_Vw,  g_Vw);
    cudaGetSymbolAddress((void**)&p_Vd,  g_Vd);
    cudaGetSymbolAddress((void**)&p_V2s, g_V2s);
    cudaGetSymbolAddress((void**)&p_V2w, g_V2w);
    cudaGetSymbolAddress((void**)&p_V2d, g_V2d);
    cudaGetSymbolAddress((void**)&p_Lw,  g_Lw);
    cudaGetSymbolAddress((void**)&p_Ld,  g_Ld);
    cudaGetSymbolAddress((void**)&p_L2w, g_L2w);
    cudaGetSymbolAddress((void**)&p_L2d, g_L2d);
    cudaGetSymbolAddress((void**)&p_xsp, g_xsp);
    cudaGetSymbolAddress((void**)&p_xwp, g_xwp);
    cudaGetSymbolAddress((void**)&p_xdp, g_xdp);
    cudaGetSymbolAddress((void**)&p_hsp, g_hsp);
    cudaGetSymbolAddress((void**)&p_hwp, g_hwp);
    cudaGetSymbolAddress((void**)&p_hdp, g_hdp);
    cudaGetSymbolAddress((void**)&p_s1p, g_s1p);
    cudaGetSymbolAddress((void**)&p_w1p, g_w1p);
    cudaGetSymbolAddress((void**)&p_d1p, g_d1p);
    cudaGetSymbolAddress((void**)&p_sop, g_sop);
    cudaGetSymbolAddress((void**)&p_p1p, g_p1p);
    cudaGetSymbolAddress((void**)&p_Wlp, g_Wlp);
    cudaGetSymbolAddress((void**)&p_B1p, g_B1p);
    cudaGetSymbolAddress((void**)&p_B2p, g_B2p);
    cudaGetSymbolAddress((void**)&p_Wp1p, g_Wp1p);
    cudaGetSymbolAddress((void**)&p_Wp2p, g_Wp2p);

    const bool dual = (g_sp.s1 != nullptr);
    cudaStream_t S0 = 0;
    cudaStream_t S1 = dual ? g_sp.s1 : (cudaStream_t)0;
    auto rec = [&](cudaEvent_t e, cudaStream_t s) { if (dual) cudaEventRecord(e, s); };
    auto wai = [&](cudaStream_t s, cudaEvent_t e) { if (dual) cudaStreamWaitEvent(s, e, 0); };

    const dim3 tb(32, 8);
    const size_t wl = (size_t)DIN * DIN;

    // ===== FORK =====
    rec(g_sp.evF, S0);
    wai(S1, g_sp.evF);

    // ===== S0: Wl weight converts =====
    convert_w_kernel<<<dim3(DIN/32, DIN/32, 1), tb, 0, S0>>>(Wls, p_Wlp + 0*wl, DIN, DIN);
    convert_w_kernel<<<dim3(DIN/32, DIN/32, 1), tb, 0, S0>>>(Wlw, p_Wlp + 1*wl, DIN, DIN);
    convert_w_kernel<<<dim3(DIN/32, DIN/32, 1), tb, 0, S0>>>(Wld, p_Wlp + 2*wl, DIN, DIN);
    rec(g_sp.evA, S0);

    // ===== S1: B-plane production + w/d chain =====
    convert_w_kernel<<<dim3(HC1/32, DIN/32, 6), tb, 0, S1>>>(W1s, p_B1p, DIN, HC1);
    convert_w_kernel<<<dim3(OUT2/32, HC1/32, 6), tb, 0, S1>>>(W2s, p_B2p, HC1, OUT2);
    convert_w_kernel<<<dim3(PROJ1/32, OUT2/32, 1), tb, 0, S1>>>(Wp1, p_Wp1p, OUT2, PROJ1);
    convert_w_kernel<<<dim3(PROJ2/32, PROJ1/32, 1), tb, 0, S1>>>(Wp2, p_Wp2p, PROJ1, PROJ2);
    {
        size_t t6a = (size_t)6 * 256 * 768;
        cudaMemsetAsync(p_B1p + t6a, 0, (size_t)256 * 768 * 2, S1);
        size_t t6b = (size_t)6 * 256 * 256;
        cudaMemsetAsync(p_B2p + t6b, 0, (size_t)256 * 256 * 2, S1);
    }
    {
        FMap fs1 = { {p_Vs, p_Vs, p_Vw, p_Vs, p_Vd, p_Vs},
                     {0, 4, 0, 8, 0, 12}, {32, 32, 8, 32, 8, 32} };
        FMap fd1 = { {p_Vs, p_Vs, p_Vs, p_Vw, p_Vs, p_Vd},
                     {16, 20, 24, 4, 28, 4}, {32, 32, 32, 8, 32, 8} };
        int tot1 = 6 * DIN * H1;
        fold_kernel<<<(tot1 * 32 + 255) / 256, 256, 0, S1>>>(W1s,  a1s, fs1, DIN, H1, C1, tot1);
        fold_kernel<<<(tot1 * 32 + 255) / 256, 256, 0, S1>>>(W1d_, a1d, fd1, DIN, H1, C1, tot1);
        FMap fs2 = { {p_V2s, p_V2s, p_V2w, p_V2w, p_V2d, p_V2d},
                     {0, 1, 0, 1, 0, 1}, {8, 8, 8, 8, 8, 8} };
        FMap fd2 = { {p_V2s, p_V2s, p_V2s, p_V2w, p_V2s, p_V2d},
                     {2, 3, 4, 2, 5, 2}, {8, 8, 8, 8, 8, 8} };
        int tot2 = 6 * HC1;
        fold_kernel<<<(tot2 * 32 + 255) / 256, 256, 0, S1>>>(W2s,  a2s, fs2, HC1, 1, OUT2, tot2);
        fold_kernel<<<(tot2 * 32 + 255) / 256, 256, 0, S1>>>(W2d_, a2d, fd2, HC1, 1, OUT2, tot2);
        size_t t6a = (size_t)6 * 256 * 768;
        v2b_kernel<<<(32 * DIN + 255) / 256, 256, 0, S1>>>(p_Vs, 32, 32, p_B1p + t6a, DIN);
        size_t t6b = (size_t)6 * 256 * 256;
        v2b_kernel<<<(8 * HC1 + 255) / 256, 256, 0, S1>>>(p_V2s, 8, 8, p_B2p + t6b, HC1);
    }
    rec(g_sp.evB1, S1);

    conv_a(S1, x_word, p_xwp, (size_t)NW * DIN);
    conv_a(S1, x_doc,  p_xdp, (size_t)ND * DIN);
    wai(S1, g_sp.evA);
    gemm_h(S1, p_xwp, (size_t)NW*DIN, p_Wlp + 1*wl, DIN, 1, blw, nullptr, nullptr,
           p_hwp, p_hwp + (size_t)NW*DIN, NW, DIN, DIN, 1, gm_uniform(0, 6));
    gemm_h(S1, p_xdp, (size_t)ND*DIN, p_Wlp + 2*wl, DIN, 1, bld, nullptr, nullptr,
           p_hdp, p_hdp + (size_t)ND*DIN, ND, DIN, DIN, 1, gm_uniform(0, 6));
    gemm_h(S1, p_hwp, (size_t)NW*DIN, p_B1p, 256, 7, nullptr, nullptr, p_Mw, nullptr, nullptr,
           NW, HC1, DIN, 0, gm_uniform(2, 2));
    gemm_h(S1, p_hdp, (size_t)ND*DIN, p_B1p, 256, 7, nullptr, nullptr, p_Md, nullptr, nullptr,
           ND, HC1, DIN, 0, gm_uniform(4, 2));
    logit8p_kernel<<<(NW + 7) / 8, 256, DIN * 9 * 4, S1>>>(p_hwp, p_hwp + (size_t)NW*DIN, p_Vw, p_Lw, NW, DIN);
    logit8p_kernel<<<(ND + 7) / 8, 256, DIN * 9 * 4, S1>>>(p_hdp, p_hdp + (size_t)ND*DIN, p_Vd, p_Ld, ND, DIN);
    cudaMemsetAsync(p_acc4,  0, (size_t)4 * NS * HC1 * 4, S1);
    cudaMemsetAsync(p_acc4b, 0, (size_t)4 * NS * HC1 * 4, S1);
    cudaMemsetAsync(p_accw,  0, (size_t)NW * HC1 * 4, S1);
    cudaMemsetAsync(p_accd,  0, (size_t)ND * HC1 * 4, S1);
    cudaMemsetAsync(p_den,   0, (size_t)6 * NW * H1 * 4, S1);
    cudaMemsetAsync(p_den2,  0, (size_t)4 * NS * 4, S1);
    rec(g_sp.evB, S1);

    // ===== S0: s-chain =====
    conv_a(S0, x_sent, p_xsp, (size_t)NS * DIN);
    gemm_h(S0, p_xsp, (size_t)NS*DIN, p_Wlp, DIN, 1, bls, nullptr, nullptr,
           p_hsp, p_hsp + (size_t)NS*DIN, NS, DIN, DIN, 1, gm_uniform(0, 6));
    wai(S0, g_sp.evB1);
    {
        GMap ghs{};
        const int t_[9]   = {0,0,1,1,3,3,5,5,6};
        const int off_[9] = {0,128,0,128,0,128,0,128,0};
        for (int i = 0; i < 9; i++) { ghs.t[i] = t_[i]; ghs.off[i] = off_[i]; }
        gemm_h(S0, p_hsp, (size_t)NS*DIN, p_B1p, 256, 7, nullptr, nullptr, p_M, nullptr, nullptr,
               NS, 1152, DIN, 0, ghs);
    }
    wai(S0, g_sp.evB);

    // ---- conv1 fused edge pass ----
    {
        EParams P;
        const size_t dstride = (size_t)NW * H1;
        P.t[0] = { ei_ss, E_ss, p_M, p_M, p_den + 0 * dstride, p_M,  p_acc4 + 0 * (size_t)NS * HC1,
                   1152, 1024 + 0, 1152, 1024 + 16, 1152, 0 };
        P.t[1] = { ei_sa, E_sa, p_M, p_M, p_den + 1 * dstride, p_M,  p_acc4 + 1 * (size_t)NS * HC1,
                   1152, 1024 + 4, 1152, 1024 + 20, 1152, 256 };
        P.t[2] = { ei_ws, E_ws, p_Lw, p_M, p_den + 2 * dstride, p_Mw, p_acc4 + 2 * (size_t)NS * HC1,
                   8, 0, 1152, 1024 + 24, 256, 0 };
        P.t[3] = { ei_sw, E_sw, p_M, p_Lw, p_den + 3 * dstride, p_M,  p_accw,
                   1152, 1024 + 8, 8, 4, 1152, 512 };
        P.t[4] = { ei_ds, E_ds, p_Ld, p_M, p_den + 4 * dstride, p_Md, p_acc4 + 3 * (size_t)NS * HC1,
                   8, 0, 1152, 1024 + 28, 256, 0 };
        P.t[5] = { ei_sd, E_sd, p_M, p_Ld, p_den + 5 * dstride, p_M,  p_accd,
                   1152, 1024 + 12, 8, 4, 1152, 768 };
        P.start[0] = 0;
        P.start[1] = E_ss;
        P.start[2] = E_ss + E_sa;
        P.start[3] = E_ss + E_sa + E_ws;
        P.start[4] = E_ss + E_sa + E_ws + E_sw;
        P.start[5] = E_ss + E_sa + E_ws + E_sw + E_ds;
        P.start[6] = E_ss + E_sa + E_ws + E_sw + E_ds + E_sd;
        P.nT = 6; P.H = 4; P.HC = 256; P.cshift = 6;
        edge_fused_kernel<<<(P.start[6] + 7) / 8, 256, 0, S0>>>(P);
    }

    // ---- conv1 combine: s on S0 ----
    {
        const size_t dstride = (size_t)NW * H1;
        combine_ln_kernel<<<NS, 256, 0, S0>>>(nullptr, p_s1p, p_s1p + (size_t)NS * HC1,
            p_acc4 + 0 * (size_t)NS * HC1, p_acc4 + 1 * (size_t)NS * HC1,
            p_acc4 + 2 * (size_t)NS * HC1, p_acc4 + 3 * (size_t)NS * HC1,
            p_den + 0 * dstride, p_den + 1 * dstride, p_den + 2 * dstride, p_den + 4 * dstride,
            4, b1, 0, 1, 2, 4, 4, 1);
    }
    rec(g_sp.evE1, S0);

    // ===== S1: w/d combines + conv2 side =====
    wai(S1, g_sp.evE1);
    {
        const size_t dstride = (size_t)NW * H1;
        combine_ln_kernel<<<NW, 256, 0, S1>>>(nullptr, p_w1p, p_w1p + (size_t)NW * HC1,
            p_accw, p_accw, p_accw, p_accw,
            p_den + 3 * dstride, p_den + 3 * dstride, p_den + 3 * dstride, p_den + 3 * dstride,
            1, b1, 3, 3, 3, 3, 4, 1);
        combine_ln_kernel<<<ND, 256, 0, S1>>>(nullptr, p_d1p, p_d1p + (size_t)ND * HC1,
            p_accd, p_accd, p_accd, p_accd,
            p_den + 5 * dstride, p_den + 5 * dstride, p_den + 5 * dstride, p_den + 5 * dstride,
            1, b1, 5, 5, 5, 5, 4, 1);
    }
    gemm_h(S1, p_w1p, (size_t)NW*HC1, p_B2p, 256, 7, nullptr, nullptr, p_Mw, nullptr, nullptr,
           NW, OUT2, HC1, 0, gm_uniform(2, 2));
    gemm_h(S1, p_d1p, (size_t)ND*HC1, p_B2p, 256, 7, nullptr, nullptr, p_Md, nullptr, nullptr,
           ND, OUT2, HC1, 0, gm_uniform(4, 2));
    logit8p_kernel<<<(NW + 7) / 8, 256, HC1 * 9 * 4, S1>>>(p_w1p, p_w1p + (size_t)NW*HC1, p_V2w, p_L2w, NW, HC1);
    logit8p_kernel<<<(ND + 7) / 8, 256, HC1 * 9 * 4, S1>>>(p_d1p, p_d1p + (size_t)ND*HC1, p_V2d, p_L2d, ND, HC1);
    rec(g_sp.evC, S1);

    // ===== S0: conv2 s GEMM, edge2, final =====
    {
        GMap gs1{};
        const int t_[5]   = {0,0,1,1,6};
        const int off_[5] = {0,128,0,128,0};
        for (int i = 0; i < 5; i++) { gs1.t[i] = t_[i]; gs1.off[i] = off_[i]; }
        gemm_h(S0, p_s1p, (size_t)NS*HC1, p_B2p, 256, 7, nullptr, nullptr, p_M, nullptr, nullptr,
               NS, 640, HC1, 0, gs1);
    }
    wai(S0, g_sp.evC);
    {
        EParams P;
        P.t[0] = { ei_ss, E_ss, p_M, p_M, p_den2 + 0 * (size_t)NS, p_M,  p_acc4b + 0 * (size_t)NS * HC1,
                   640, 512 + 0, 640, 512 + 2, 640, 0 };
        P.t[1] = { ei_sa, E_sa, p_M, p_M, p_den2 + 1 * (size_t)NS, p_M,  p_acc4b + 1 * (size_t)NS * HC1,
                   640, 512 + 1, 640, 512 + 3, 640, 256 };
        P.t[2] = { ei_ws, E_ws, p_L2w, p_M, p_den2 + 2 * (size_t)NS, p_Mw, p_acc4b + 2 * (size_t)NS * HC1,
                   8, 0, 640, 512 + 4, 256, 0 };
        P.t[3] = { ei_ds, E_ds, p_L2d, p_M, p_den2 + 3 * (size_t)NS, p_Md, p_acc4b + 3 * (size_t)NS * HC1,
                   8, 0, 640, 512 + 5, 256, 0 };
        P.t[4] = P.t[0];
        P.t[5] = P.t[0];
        P.start[0] = 0;
        P.start[1] = E_ss;
        P.start[2] = E_ss + E_sa;
        P.start[3] = E_ss + E_sa + E_ws;
        P.start[4] = E_ss + E_sa + E_ws + E_ds;
        P.start[5] = P.start[4];
        P.start[6] = P.start[4];
        P.nT = 4; P.H = 1; P.HC = 256; P.cshift = 8;
        edge_fused_kernel<<<(P.start[4] + 7) / 8, 256, 0, S0>>>(P);
    }
    combine_ln_kernel<<<NS, 256, 0, S0>>>(out_f, p_sop, p_sop + (size_t)NS * OUT2,
        p_acc4b + 0 * (size_t)NS * HC1, p_acc4b + 1 * (size_t)NS * HC1,
        p_acc4b + 2 * (size_t)NS * HC1, p_acc4b + 3 * (size_t)NS * HC1,
        p_den2 + 0 * (size_t)NS, p_den2 + 1 * (size_t)NS,
        p_den2 + 2 * (size_t)NS, p_den2 + 3 * (size_t)NS,
        4, b2, 0, 1, 2, 4, 1, 0);

    if (out_size >= NS * (OUT2 + PROJ2)) {
        gemm_h(S0, p_sop, (size_t)NS*OUT2, p_Wp1p, PROJ1, 1, bp1, nullptr, nullptr,
               p_p1p, p_p1p + (size_t)NS*PROJ1, NS, PROJ1, OUT2, 1, gm_uniform(0, 1));
        gemm_h(S0, p_p1p, (size_t)NS*PROJ1, p_Wp2p, PROJ2, 1, bp2,
               out_f + (size_t)NS * OUT2, nullptr, nullptr, nullptr,
               NS, PROJ2, PROJ1, 0, gm_uniform(0, 1));
    }
    // Join complete: every S1 op precedes evC, which S0 waits on.
}